// round 1
// baseline (speedup 1.0000x reference)
#include <cuda_runtime.h>

// ---------------------------------------------------------------------------
// Fused sparse-conv block:
//   h1 = relu(sconv(feats, W1a) + b1a)
//   h2 = (sconv(h1, W1b) + b1b) * beta + gamma        (beta|gamma = cond split)
//   h3 = relu(sconv(h2, W2a) + b2a)
//   out = relu(sconv(h3, W2b) + b2b) + feats
// sconv(x)[p] = sum_k  x[nbr[p,k]] @ W[k]   (nbr<0 => skip)
// ---------------------------------------------------------------------------

#define N_CH 64
#define MAXP 250016   // P <= 4 * 62500 = 250000

__device__ float g_buf1[(size_t)MAXP * N_CH];
__device__ float g_buf2[(size_t)MAXP * N_CH];

// MODE 0: relu(acc + b)
// MODE 1: (acc + b) * beta + gamma   (extra = cond, [P,128])
// MODE 3: relu(acc + b) + extra[p]   (extra = feats, [P,64])
template <int MODE>
__global__ __launch_bounds__(256, 4) void sconv_kernel(
    const float* __restrict__ x,     // [P,64]
    const int*   __restrict__ nbr,   // [P,27]
    const float* __restrict__ W,     // [27,64,64]
    const float* __restrict__ bias,  // [64]
    const float* __restrict__ extra, // cond / feats / nullptr
    float*       __restrict__ out,   // [P,64]
    int P)
{
    __shared__ float Xs[64][65];     // gathered rows, padded (bank-conflict-free)
    __shared__ float Ws[64][64];     // W[k], row i = input channel
    __shared__ int   nbs[64 * 27];   // neighbor tile

    const int tid = threadIdx.x;
    const int p0  = blockIdx.x * 64;

    // stage neighbor indices for this 64-point tile
    for (int t = tid; t < 64 * 27; t += 256) {
        int row = t / 27;
        int p   = p0 + row;
        nbs[t]  = (p < P) ? nbr[(size_t)p * 27 + (t % 27)] : -1;
    }
    __syncthreads();

    const int ty = tid >> 4;   // 0..15 -> 4 output rows each
    const int tx = tid & 15;   // 0..15 -> 4 output cols each

    const int grow = tid >> 2; // gather: row 0..63
    const int gseg = tid & 3;  // gather: 16-float segment 0..3

    float acc[4][4];
#pragma unroll
    for (int r = 0; r < 4; ++r)
#pragma unroll
        for (int c = 0; c < 4; ++c) acc[r][c] = 0.f;

    for (int k = 0; k < 27; ++k) {
        // --- stage W[k] (64x64 fp32, vectorized) ---
        const float4* Wg  = (const float4*)(W + (size_t)k * 64 * 64);
        float4*       Wsv = (float4*)&Ws[0][0];
#pragma unroll
        for (int t = 0; t < 4; ++t)
            Wsv[tid + t * 256] = Wg[tid + t * 256];

        // --- gather X rows (4 threads per row, 16 floats each) ---
        {
            int n = nbs[grow * 27 + k];
            int cbase = gseg * 16;
            if (n >= 0) {
                const float4* xr = (const float4*)(x + (size_t)n * N_CH) + gseg * 4;
#pragma unroll
                for (int t = 0; t < 4; ++t) {
                    float4 v = xr[t];
                    int c = cbase + t * 4;
                    Xs[grow][c + 0] = v.x; Xs[grow][c + 1] = v.y;
                    Xs[grow][c + 2] = v.z; Xs[grow][c + 3] = v.w;
                }
            } else {
#pragma unroll
                for (int t = 0; t < 4; ++t) {
                    int c = cbase + t * 4;
                    Xs[grow][c + 0] = 0.f; Xs[grow][c + 1] = 0.f;
                    Xs[grow][c + 2] = 0.f; Xs[grow][c + 3] = 0.f;
                }
            }
        }
        __syncthreads();

        // --- 64x64x64 tile GEMM, 4x4 micro-tile per thread ---
#pragma unroll 16
        for (int i = 0; i < 64; ++i) {
            float x0 = Xs[ty * 4 + 0][i];
            float x1 = Xs[ty * 4 + 1][i];
            float x2 = Xs[ty * 4 + 2][i];
            float x3 = Xs[ty * 4 + 3][i];
            float4 wv = *(const float4*)&Ws[i][tx * 4];
            acc[0][0] += x0 * wv.x; acc[0][1] += x0 * wv.y;
            acc[0][2] += x0 * wv.z; acc[0][3] += x0 * wv.w;
            acc[1][0] += x1 * wv.x; acc[1][1] += x1 * wv.y;
            acc[1][2] += x1 * wv.z; acc[1][3] += x1 * wv.w;
            acc[2][0] += x2 * wv.x; acc[2][1] += x2 * wv.y;
            acc[2][2] += x2 * wv.z; acc[2][3] += x2 * wv.w;
            acc[3][0] += x3 * wv.x; acc[3][1] += x3 * wv.y;
            acc[3][2] += x3 * wv.z; acc[3][3] += x3 * wv.w;
        }
        __syncthreads();
    }

    // --- epilogue ---
    const float4 bv = *(const float4*)(bias + tx * 4);
#pragma unroll
    for (int r = 0; r < 4; ++r) {
        int p = p0 + ty * 4 + r;
        if (p >= P) continue;
        float v0 = acc[r][0] + bv.x;
        float v1 = acc[r][1] + bv.y;
        float v2 = acc[r][2] + bv.z;
        float v3 = acc[r][3] + bv.w;
        if (MODE == 0) {
            v0 = fmaxf(v0, 0.f); v1 = fmaxf(v1, 0.f);
            v2 = fmaxf(v2, 0.f); v3 = fmaxf(v3, 0.f);
        } else if (MODE == 1) {
            const float4 be = *(const float4*)(extra + (size_t)p * 128 + tx * 4);
            const float4 ga = *(const float4*)(extra + (size_t)p * 128 + 64 + tx * 4);
            v0 = v0 * be.x + ga.x; v1 = v1 * be.y + ga.y;
            v2 = v2 * be.z + ga.z; v3 = v3 * be.w + ga.w;
        } else if (MODE == 3) {
            const float4 res = *(const float4*)(extra + (size_t)p * N_CH + tx * 4);
            v0 = fmaxf(v0, 0.f) + res.x; v1 = fmaxf(v1, 0.f) + res.y;
            v2 = fmaxf(v2, 0.f) + res.z; v3 = fmaxf(v3, 0.f) + res.w;
        }
        *(float4*)(out + (size_t)p * N_CH + tx * 4) = make_float4(v0, v1, v2, v3);
    }
}

extern "C" void kernel_launch(void* const* d_in, const int* in_sizes, int n_in,
                              void* d_out, int out_size)
{
    const float* feats = (const float*)d_in[0];
    const float* cond  = (const float*)d_in[1];
    const float* W1a   = (const float*)d_in[2];
    const float* b1a   = (const float*)d_in[3];
    const float* W1b   = (const float*)d_in[4];
    const float* b1b   = (const float*)d_in[5];
    const float* W2a   = (const float*)d_in[6];
    const float* b2a   = (const float*)d_in[7];
    const float* W2b   = (const float*)d_in[8];
    const float* b2b   = (const float*)d_in[9];
    const int*   nbr   = (const int*)d_in[10];

    int P = in_sizes[0] / N_CH;
    float* out = (float*)d_out;

    float *h1, *h2;
    cudaGetSymbolAddress((void**)&h1, g_buf1);
    cudaGetSymbolAddress((void**)&h2, g_buf2);

    int grid = (P + 63) / 64;

    sconv_kernel<0><<<grid, 256>>>(feats, nbr, W1a, b1a, nullptr, h1, P);
    sconv_kernel<1><<<grid, 256>>>(h1,    nbr, W1b, b1b, cond,    h2, P);
    sconv_kernel<0><<<grid, 256>>>(h2,    nbr, W2a, b2a, nullptr, h1, P);
    sconv_kernel<3><<<grid, 256>>>(h1,    nbr, W2b, b2b, feats,  out, P);
}

// round 3
// speedup vs baseline: 2.1421x; 2.1421x over previous
#include <cuda_runtime.h>
#include <cuda_bf16.h>
#include <cstdint>

// ---------------------------------------------------------------------------
// Fused sparse-conv block on tensor cores via baseline-PTX mma.sync (HMMA),
// bf16 hi/lo 3-pass split (hi*hi + hi*lo + lo*hi) for ~fp32 accuracy.
//   sconv(x)[p] = sum_{k=0..26} x[nbr[p,k]] @ W[k]
//   out = relu(sconv(relu(sconv(film(sconv(relu(sconv(f,W1a)),W1b)),W2a)),W2b)) + f
// CTA tile: M=128 points x N=64 ch. 8 warps; warp w owns rows [16w,16w+16),
// all 64 output cols. Register accumulators across all taps/passes.
// ---------------------------------------------------------------------------

typedef __nv_bfloat16 bf16;
#define N_CH 64
#define MAXP 250048

__device__ bf16 g_fhi[(size_t)MAXP * N_CH];
__device__ bf16 g_flo[(size_t)MAXP * N_CH];
__device__ bf16 g_ahi[(size_t)MAXP * N_CH];
__device__ bf16 g_alo[(size_t)MAXP * N_CH];
__device__ bf16 g_bhi[(size_t)MAXP * N_CH];
__device__ bf16 g_blo[(size_t)MAXP * N_CH];
__device__ bf16 g_whi[4 * 27 * 64 * 64];
__device__ bf16 g_wlo[4 * 27 * 64 * 64];

// ---- smem layout (bytes). Row pitch 144B (72 bf16) => conflict-free frags.
#define PITCH     144
#define OFF_BIAS  32
#define OFF_NBS   288                  // 128*27 ints = 13824
#define OFF_BUF   14336                // stages
#define A_HI      0                    // 128 rows * 144B = 18432
#define A_LO      18432
#define B_HI      36864                // 64 rows * 144B = 9216
#define B_LO      46080
#define STAGE_SZ  55296
#define SMEM_TOTAL (OFF_BUF + 2 * STAGE_SZ)   // 124928

// ---------------- PTX helpers ----------------
__device__ __forceinline__ void cp16(void* dst, const void* src) {
    uint32_t d;
    asm("{ .reg .u64 t; cvta.to.shared.u64 t, %1; cvt.u32.u64 %0, t; }" : "=r"(d) : "l"(dst));
    asm volatile("cp.async.ca.shared.global [%0], [%1], 16;" :: "r"(d), "l"(src));
}
__device__ __forceinline__ void zero16(void* dst) {
    *(float4*)dst = make_float4(0.f, 0.f, 0.f, 0.f);
}
#define CP_COMMIT() asm volatile("cp.async.commit_group;" ::: "memory")
#define CP_WAIT1()  asm volatile("cp.async.wait_group 1;" ::: "memory")
#define CP_WAIT0()  asm volatile("cp.async.wait_group 0;" ::: "memory")

__device__ __forceinline__ void mma_bf16(float* c, const uint32_t* a, const uint32_t* b) {
    asm volatile(
        "mma.sync.aligned.m16n8k16.row.col.f32.bf16.bf16.f32 "
        "{%0,%1,%2,%3}, {%4,%5,%6,%7}, {%8,%9}, {%0,%1,%2,%3};"
        : "+f"(c[0]), "+f"(c[1]), "+f"(c[2]), "+f"(c[3])
        : "r"(a[0]), "r"(a[1]), "r"(a[2]), "r"(a[3]), "r"(b[0]), "r"(b[1]));
}

// ---------------- prep kernels ----------------
__global__ void prep_weights(const float* __restrict__ W0, const float* __restrict__ W1,
                             const float* __restrict__ W2, const float* __restrict__ W3,
                             bf16* __restrict__ whi, bf16* __restrict__ wlo) {
    int layer = blockIdx.y;
    int i = blockIdx.x * 256 + threadIdx.x;          // over 27*64*64
    if (i >= 27 * 4096) return;
    const float* W = (layer == 0) ? W0 : (layer == 1) ? W1 : (layer == 2) ? W2 : W3;
    int k = i >> 12, n = (i >> 6) & 63, kk = i & 63;
    float w = W[((size_t)k * 64 + kk) * 64 + n];     // store as [k][n][kk] (B col-major)
    bf16 h = __float2bfloat16(w);
    size_t o = (size_t)layer * 27 * 4096 + i;
    whi[o] = h;
    wlo[o] = __float2bfloat16(w - __bfloat162float(h));
}

__global__ void prep_feats(const float* __restrict__ f, bf16* __restrict__ fhi,
                           bf16* __restrict__ flo, int n) {
    int i = blockIdx.x * 256 + threadIdx.x;
    if (i >= n) return;
    float v = f[i];
    bf16 h = __float2bfloat16(v);
    fhi[i] = h;
    flo[i] = __float2bfloat16(v - __bfloat162float(h));
}

// ---------------- main conv kernel ----------------
// MODE 0: h = relu(acc+b)            -> bf16 hi/lo out
// MODE 1: h = (acc+b)*beta + gamma   -> bf16 hi/lo out  (extra = cond [P,128])
// MODE 3: h = relu(acc+b) + extra    -> fp32 out        (extra = feats [P,64])
template <int MODE>
__global__ __launch_bounds__(256, 1) void conv_mma(
    const bf16* __restrict__ xhi, const bf16* __restrict__ xlo,
    const int*  __restrict__ nbr,
    const bf16* __restrict__ whi, const bf16* __restrict__ wlo,
    const float* __restrict__ bias, const float* __restrict__ extra,
    float* __restrict__ outf, bf16* __restrict__ outhi, bf16* __restrict__ outlo,
    int P)
{
    extern __shared__ char smem[];
    const int tid = threadIdx.x;
    const int wid = tid >> 5;
    const int lane = tid & 31;
    const int p0  = blockIdx.x * 128;

    int*   nbs     = (int*)(smem + OFF_NBS);
    float* bias_sm = (float*)(smem + OFF_BIAS);

    if (tid < 64) bias_sm[tid] = bias[tid];
    for (int t = tid; t < 128 * 27; t += 256) {
        int row = t / 27, p = p0 + row;
        nbs[t] = (p < P) ? nbr[(size_t)p * 27 + (t - row * 27)] : -1;
    }
    __syncthreads();

    auto gather = [&](int k, int stg) {
        char* base = smem + OFF_BUF + stg * STAGE_SZ;
        // A: 128 rows x 128B, hi+lo  (2048 16B-chunks)
        #pragma unroll
        for (int it = 0; it < 8; ++it) {
            int task = it * 256 + tid;
            int half = task >> 10;
            int rc   = task & 1023;
            int row  = rc >> 3;
            int c    = rc & 7;
            int n    = nbs[row * 27 + k];
            char* dst = base + (half ? A_LO : A_HI) + row * PITCH + c * 16;
            if (n >= 0)
                cp16(dst, (half ? xlo : xhi) + (size_t)n * 64 + c * 8);
            else
                zero16(dst);
        }
        // B: 64 rows x 128B, hi+lo (1024 16B-chunks)
        const bf16* wb_hi = whi + (size_t)k * 4096;
        const bf16* wb_lo = wlo + (size_t)k * 4096;
        #pragma unroll
        for (int it = 0; it < 4; ++it) {
            int task = it * 256 + tid;
            int half = task >> 9;
            int rc   = task & 511;
            int row  = rc >> 3;
            int c    = rc & 7;
            char* dst = base + (half ? B_LO : B_HI) + row * PITCH + c * 16;
            cp16(dst, (half ? wb_lo : wb_hi) + (size_t)row * 64 + c * 8);
        }
        CP_COMMIT();
    };

    gather(0, 0);
    gather(1, 1);

    float acc[8][4];
    #pragma unroll
    for (int nf = 0; nf < 8; ++nf)
        #pragma unroll
        for (int j = 0; j < 4; ++j) acc[nf][j] = 0.f;

    const int rA = lane >> 2;        // 0..7
    const int cq = lane & 3;         // 0..3

    for (int k = 0; k < 27; ++k) {
        const int s = k & 1;
        if (k < 26) CP_WAIT1(); else CP_WAIT0();
        __syncthreads();

        char* base = smem + OFF_BUF + s * STAGE_SZ;
        const char* Ah = base + A_HI + (wid * 16 + rA) * PITCH + cq * 4;
        const char* Al = base + A_LO + (wid * 16 + rA) * PITCH + cq * 4;
        const char* Bh = base + B_HI + rA * PITCH + cq * 4;
        const char* Bl = base + B_LO + rA * PITCH + cq * 4;

        #pragma unroll
        for (int ks = 0; ks < 4; ++ks) {
            const int kb = ks * 32;  // 16 bf16 = 32B per k-step
            uint32_t ah[4], al[4];
            ah[0] = *(const uint32_t*)(Ah + kb);
            ah[1] = *(const uint32_t*)(Ah + kb + 8 * PITCH);
            ah[2] = *(const uint32_t*)(Ah + kb + 16);
            ah[3] = *(const uint32_t*)(Ah + kb + 8 * PITCH + 16);
            al[0] = *(const uint32_t*)(Al + kb);
            al[1] = *(const uint32_t*)(Al + kb + 8 * PITCH);
            al[2] = *(const uint32_t*)(Al + kb + 16);
            al[3] = *(const uint32_t*)(Al + kb + 8 * PITCH + 16);

            uint32_t bh[8][2], bl[8][2];
            #pragma unroll
            for (int nf = 0; nf < 8; ++nf) {
                const char* ph = Bh + nf * 8 * PITCH + kb;
                const char* pl = Bl + nf * 8 * PITCH + kb;
                bh[nf][0] = *(const uint32_t*)ph;
                bh[nf][1] = *(const uint32_t*)(ph + 16);
                bl[nf][0] = *(const uint32_t*)pl;
                bl[nf][1] = *(const uint32_t*)(pl + 16);
            }
            #pragma unroll
            for (int nf = 0; nf < 8; ++nf) mma_bf16(acc[nf], ah, bh[nf]);
            #pragma unroll
            for (int nf = 0; nf < 8; ++nf) mma_bf16(acc[nf], ah, bl[nf]);
            #pragma unroll
            for (int nf = 0; nf < 8; ++nf) mma_bf16(acc[nf], al, bh[nf]);
        }
        __syncthreads();
        if (k + 2 < 27) gather(k + 2, s);
    }

    // ---------------- epilogue ----------------
    // C frag: c0,c1 -> row wid*16 + rA, cols nf*8 + cq*2 (+1)
    //         c2,c3 -> row wid*16 + rA + 8
    const int pA = p0 + wid * 16 + rA;
    const int pB = pA + 8;

    #pragma unroll
    for (int half = 0; half < 2; ++half) {
        const int p = half ? pB : pA;
        if (p >= P) continue;
        #pragma unroll
        for (int nf = 0; nf < 8; ++nf) {
            const int col = nf * 8 + cq * 2;
            float v0 = acc[nf][half * 2 + 0] + bias_sm[col];
            float v1 = acc[nf][half * 2 + 1] + bias_sm[col + 1];
            if (MODE == 0) {
                v0 = fmaxf(v0, 0.f); v1 = fmaxf(v1, 0.f);
            } else if (MODE == 1) {
                float2 be = *(const float2*)(extra + (size_t)p * 128 + col);
                float2 ga = *(const float2*)(extra + (size_t)p * 128 + 64 + col);
                v0 = v0 * be.x + ga.x;
                v1 = v1 * be.y + ga.y;
            } else { // MODE 3
                float2 rs = *(const float2*)(extra + (size_t)p * 64 + col);
                v0 = fmaxf(v0, 0.f) + rs.x;
                v1 = fmaxf(v1, 0.f) + rs.y;
            }
            if (MODE == 3) {
                *(float2*)(outf + (size_t)p * 64 + col) = make_float2(v0, v1);
            } else {
                bf16 h0 = __float2bfloat16(v0), h1 = __float2bfloat16(v1);
                bf16 l0 = __float2bfloat16(v0 - __bfloat162float(h0));
                bf16 l1 = __float2bfloat16(v1 - __bfloat162float(h1));
                uint32_t hp = (uint32_t)__bfloat16_as_ushort(h0) |
                              ((uint32_t)__bfloat16_as_ushort(h1) << 16);
                uint32_t lp = (uint32_t)__bfloat16_as_ushort(l0) |
                              ((uint32_t)__bfloat16_as_ushort(l1) << 16);
                *(uint32_t*)(outhi + (size_t)p * 64 + col) = hp;
                *(uint32_t*)(outlo + (size_t)p * 64 + col) = lp;
            }
        }
    }
}

// ---------------- launch ----------------
extern "C" void kernel_launch(void* const* d_in, const int* in_sizes, int n_in,
                              void* d_out, int out_size)
{
    const float* feats = (const float*)d_in[0];
    const float* cond  = (const float*)d_in[1];
    const float* W1a   = (const float*)d_in[2];
    const float* b1a   = (const float*)d_in[3];
    const float* W1b   = (const float*)d_in[4];
    const float* b1b   = (const float*)d_in[5];
    const float* W2a   = (const float*)d_in[6];
    const float* b2a   = (const float*)d_in[7];
    const float* W2b   = (const float*)d_in[8];
    const float* b2b   = (const float*)d_in[9];
    const int*   nbr   = (const int*)d_in[10];

    int P = in_sizes[0] / N_CH;
    float* out = (float*)d_out;

    bf16 *fhi, *flo, *ahi, *alo, *bhi, *blo, *whi, *wlo;
    cudaGetSymbolAddress((void**)&fhi, g_fhi);
    cudaGetSymbolAddress((void**)&flo, g_flo);
    cudaGetSymbolAddress((void**)&ahi, g_ahi);
    cudaGetSymbolAddress((void**)&alo, g_alo);
    cudaGetSymbolAddress((void**)&bhi, g_bhi);
    cudaGetSymbolAddress((void**)&blo, g_blo);
    cudaGetSymbolAddress((void**)&whi, g_whi);
    cudaGetSymbolAddress((void**)&wlo, g_wlo);

    cudaFuncSetAttribute(conv_mma<0>, cudaFuncAttributeMaxDynamicSharedMemorySize, SMEM_TOTAL);
    cudaFuncSetAttribute(conv_mma<1>, cudaFuncAttributeMaxDynamicSharedMemorySize, SMEM_TOTAL);
    cudaFuncSetAttribute(conv_mma<3>, cudaFuncAttributeMaxDynamicSharedMemorySize, SMEM_TOTAL);

    {
        dim3 g((27 * 4096 + 255) / 256, 4);
        prep_weights<<<g, 256>>>(W1a, W1b, W2a, W2b, whi, wlo);
    }
    prep_feats<<<(P * N_CH + 255) / 256, 256>>>(feats, fhi, flo, P * N_CH);

    const size_t LW = (size_t)27 * 4096;
    int grid = (P + 127) / 128;
    conv_mma<0><<<grid, 256, SMEM_TOTAL>>>(fhi, flo, nbr, whi + 0 * LW, wlo + 0 * LW,
                                           b1a, nullptr, nullptr, ahi, alo, P);
    conv_mma<1><<<grid, 256, SMEM_TOTAL>>>(ahi, alo, nbr, whi + 1 * LW, wlo + 1 * LW,
                                           b1b, cond, nullptr, bhi, blo, P);
    conv_mma<0><<<grid, 256, SMEM_TOTAL>>>(bhi, blo, nbr, whi + 2 * LW, wlo + 2 * LW,
                                           b2a, nullptr, nullptr, ahi, alo, P);
    conv_mma<3><<<grid, 256, SMEM_TOTAL>>>(ahi, alo, nbr, whi + 3 * LW, wlo + 3 * LW,
                                           b2b, feats, out, nullptr, nullptr, P);
}

// round 4
// speedup vs baseline: 2.7932x; 1.3039x over previous
#include <cuda_runtime.h>
#include <cuda_bf16.h>
#include <cstdint>

// ---------------------------------------------------------------------------
// Fused sparse-conv block via mma.sync bf16 hi/lo 3-pass split (~fp32 acc).
// R4: swizzled 128B-pitch smem (2 CTAs/SM) + 4 warps x (64x32) square tiles
//     to cut smem crossbar traffic (B-fragment duplication) ~25%.
// CTA tile: M=128 x N=64. Warp (wy,wx): rows wy*64+[0,64), cols wx*32+[0,32).
// ---------------------------------------------------------------------------

typedef __nv_bfloat16 bf16;
#define N_CH 64
#define MAXP 250048

__device__ bf16 g_fhi[(size_t)MAXP * N_CH];
__device__ bf16 g_flo[(size_t)MAXP * N_CH];
__device__ bf16 g_ahi[(size_t)MAXP * N_CH];
__device__ bf16 g_alo[(size_t)MAXP * N_CH];
__device__ bf16 g_bhi[(size_t)MAXP * N_CH];
__device__ bf16 g_blo[(size_t)MAXP * N_CH];
__device__ bf16 g_whi[4 * 27 * 64 * 64];
__device__ bf16 g_wlo[4 * 27 * 64 * 64];

// ---- smem layout. 128B row pitch + XOR-16B-chunk swizzle (conflict-free).
#define OFF_BIAS  0                    // 64 floats = 256
#define OFF_NBS   256                  // 128*27 ints = 13824 -> 14080
#define OFF_BUF   14336                // 1024-aligned
#define A_HI      0                    // 128 rows * 128B = 16384
#define A_LO      16384
#define B_HI      32768                // 64 rows * 128B = 8192
#define B_LO      40960
#define STAGE_SZ  49152
#define SMEM_TOTAL (OFF_BUF + 2 * STAGE_SZ)   // 112640 -> 2 CTAs/SM

// ---------------- PTX helpers ----------------
__device__ __forceinline__ void cp16(void* dst, const void* src) {
    uint32_t d;
    asm("{ .reg .u64 t; cvta.to.shared.u64 t, %1; cvt.u32.u64 %0, t; }" : "=r"(d) : "l"(dst));
    asm volatile("cp.async.ca.shared.global [%0], [%1], 16;" :: "r"(d), "l"(src));
}
__device__ __forceinline__ void zero16(void* dst) {
    *(float4*)dst = make_float4(0.f, 0.f, 0.f, 0.f);
}
#define CP_COMMIT() asm volatile("cp.async.commit_group;" ::: "memory")
#define CP_WAIT1()  asm volatile("cp.async.wait_group 1;" ::: "memory")
#define CP_WAIT0()  asm volatile("cp.async.wait_group 0;" ::: "memory")

__device__ __forceinline__ void mma_bf16(float* c, const uint32_t* a, const uint32_t* b) {
    asm volatile(
        "mma.sync.aligned.m16n8k16.row.col.f32.bf16.bf16.f32 "
        "{%0,%1,%2,%3}, {%4,%5,%6,%7}, {%8,%9}, {%0,%1,%2,%3};"
        : "+f"(c[0]), "+f"(c[1]), "+f"(c[2]), "+f"(c[3])
        : "r"(a[0]), "r"(a[1]), "r"(a[2]), "r"(a[3]), "r"(b[0]), "r"(b[1]));
}

// ---------------- prep kernels ----------------
__global__ void prep_weights(const float* __restrict__ W0, const float* __restrict__ W1,
                             const float* __restrict__ W2, const float* __restrict__ W3,
                             bf16* __restrict__ whi, bf16* __restrict__ wlo) {
    int layer = blockIdx.y;
    int i = blockIdx.x * 256 + threadIdx.x;          // over 27*64*64
    if (i >= 27 * 4096) return;
    const float* W = (layer == 0) ? W0 : (layer == 1) ? W1 : (layer == 2) ? W2 : W3;
    int k = i >> 12, n = (i >> 6) & 63, kk = i & 63;
    float w = W[((size_t)k * 64 + kk) * 64 + n];     // store [k][n][kk] (B col-major)
    bf16 h = __float2bfloat16(w);
    size_t o = (size_t)layer * 27 * 4096 + i;
    whi[o] = h;
    wlo[o] = __float2bfloat16(w - __bfloat162float(h));
}

__global__ void prep_feats(const float* __restrict__ f, bf16* __restrict__ fhi,
                           bf16* __restrict__ flo, int n) {
    int i = blockIdx.x * 256 + threadIdx.x;
    if (i >= n) return;
    float v = f[i];
    bf16 h = __float2bfloat16(v);
    fhi[i] = h;
    flo[i] = __float2bfloat16(v - __bfloat162float(h));
}

// ---------------- main conv kernel ----------------
// MODE 0: h = relu(acc+b)            -> bf16 hi/lo out
// MODE 1: h = (acc+b)*beta + gamma   -> bf16 hi/lo out  (extra = cond [P,128])
// MODE 3: h = relu(acc+b) + extra    -> fp32 out        (extra = feats [P,64])
template <int MODE>
__global__ __launch_bounds__(128, 2) void conv_mma(
    const bf16* __restrict__ xhi, const bf16* __restrict__ xlo,
    const int*  __restrict__ nbr,
    const bf16* __restrict__ whi, const bf16* __restrict__ wlo,
    const float* __restrict__ bias, const float* __restrict__ extra,
    float* __restrict__ outf, bf16* __restrict__ outhi, bf16* __restrict__ outlo,
    int P)
{
    extern __shared__ char smem[];
    const int tid  = threadIdx.x;
    const int wid  = tid >> 5;
    const int lane = tid & 31;
    const int wy   = wid >> 1;        // 0..1 : M half (64 rows)
    const int wx   = wid & 1;         // 0..1 : N half (32 cols)
    const int rA   = lane >> 2;       // 0..7
    const int cq   = lane & 3;        // 0..3
    const int p0   = blockIdx.x * 128;

    int*   nbs     = (int*)(smem + OFF_NBS);
    float* bias_sm = (float*)(smem + OFF_BIAS);

    if (tid < 64) bias_sm[tid] = bias[tid];
    for (int t = tid; t < 128 * 27; t += 128) {
        int row = t / 27, p = p0 + row;
        nbs[t] = (p < P) ? nbr[(size_t)p * 27 + (t - row * 27)] : -1;
    }
    __syncthreads();

    auto gather = [&](int k, int stg) {
        char* base = smem + OFF_BUF + stg * STAGE_SZ;
        // A: 128 rows x 8 chunks x hi/lo = 2048 chunks
        #pragma unroll
        for (int it = 0; it < 16; ++it) {
            int task = it * 128 + tid;
            int half = task >> 10;
            int rc   = task & 1023;
            int row  = rc >> 3;
            int c    = rc & 7;
            int n    = nbs[row * 27 + k];
            char* dst = base + (half ? A_LO : A_HI) + row * 128 + ((c ^ (row & 7)) << 4);
            if (n >= 0)
                cp16(dst, (half ? xlo : xhi) + (size_t)n * 64 + c * 8);
            else
                zero16(dst);
        }
        // B: 64 rows x 8 chunks x hi/lo = 1024 chunks
        const bf16* wb_hi = whi + (size_t)k * 4096;
        const bf16* wb_lo = wlo + (size_t)k * 4096;
        #pragma unroll
        for (int it = 0; it < 8; ++it) {
            int task = it * 128 + tid;
            int half = task >> 9;
            int rc   = task & 511;
            int row  = rc >> 3;
            int c    = rc & 7;
            char* dst = base + (half ? B_LO : B_HI) + row * 128 + ((c ^ (row & 7)) << 4);
            cp16(dst, (half ? wb_lo : wb_hi) + (size_t)row * 64 + c * 8);
        }
        CP_COMMIT();
    };

    gather(0, 0);
    gather(1, 1);

    float acc[4][4][4];               // [m-tile][n-frag][frag]
    #pragma unroll
    for (int t = 0; t < 4; ++t)
        #pragma unroll
        for (int j = 0; j < 4; ++j)
            #pragma unroll
            for (int q = 0; q < 4; ++q) acc[t][j][q] = 0.f;

    const uint32_t sw = (uint32_t)(rA << 4);   // row&7 == rA for all tiles used

    for (int k = 0; k < 27; ++k) {
        const int s = k & 1;
        if (k < 26) CP_WAIT1(); else CP_WAIT0();
        __syncthreads();

        char* base = smem + OFF_BUF + s * STAGE_SZ;
        // warp base rows: A row0 = wy*64 + rA ; B row0 = wx*32 + rA
        const char* Ah = base + A_HI + (wy * 64 + rA) * 128;
        const char* Al = base + A_LO + (wy * 64 + rA) * 128;
        const char* Bh = base + B_HI + (wx * 32 + rA) * 128;
        const char* Bl = base + B_LO + (wx * 32 + rA) * 128;

        #pragma unroll
        for (int ks = 0; ks < 4; ++ks) {
            const uint32_t c0 = (uint32_t)(ks * 32 + cq * 4) ^ sw;       // k-lo
            const uint32_t c1 = (uint32_t)(ks * 32 + 16 + cq * 4) ^ sw;  // k-hi

            uint32_t ah[4][4], al[4][4];
            #pragma unroll
            for (int t = 0; t < 4; ++t) {
                const char* ph = Ah + t * 2048;   // +16 rows
                const char* pl = Al + t * 2048;
                ah[t][0] = *(const uint32_t*)(ph + c0);
                ah[t][1] = *(const uint32_t*)(ph + 1024 + c0);  // +8 rows
                ah[t][2] = *(const uint32_t*)(ph + c1);
                ah[t][3] = *(const uint32_t*)(ph + 1024 + c1);
                al[t][0] = *(const uint32_t*)(pl + c0);
                al[t][1] = *(const uint32_t*)(pl + 1024 + c0);
                al[t][2] = *(const uint32_t*)(pl + c1);
                al[t][3] = *(const uint32_t*)(pl + 1024 + c1);
            }
            uint32_t bh[4][2], bl[4][2];
            #pragma unroll
            for (int j = 0; j < 4; ++j) {
                const char* ph = Bh + j * 1024;   // +8 n-rows
                const char* pl = Bl + j * 1024;
                bh[j][0] = *(const uint32_t*)(ph + c0);
                bh[j][1] = *(const uint32_t*)(ph + c1);
                bl[j][0] = *(const uint32_t*)(pl + c0);
                bl[j][1] = *(const uint32_t*)(pl + c1);
            }
            #pragma unroll
            for (int t = 0; t < 4; ++t)
                #pragma unroll
                for (int j = 0; j < 4; ++j) mma_bf16(acc[t][j], ah[t], bh[j]);
            #pragma unroll
            for (int t = 0; t < 4; ++t)
                #pragma unroll
                for (int j = 0; j < 4; ++j) mma_bf16(acc[t][j], ah[t], bl[j]);
            #pragma unroll
            for (int t = 0; t < 4; ++t)
                #pragma unroll
                for (int j = 0; j < 4; ++j) mma_bf16(acc[t][j], al[t], bh[j]);
        }
        __syncthreads();
        if (k + 2 < 27) gather(k + 2, s);
    }

    // ---------------- epilogue ----------------
    #pragma unroll
    for (int t = 0; t < 4; ++t) {
        #pragma unroll
        for (int half = 0; half < 2; ++half) {
            const int p = p0 + wy * 64 + t * 16 + rA + half * 8;
            if (p >= P) continue;
            #pragma unroll
            for (int j = 0; j < 4; ++j) {
                const int col = wx * 32 + j * 8 + cq * 2;
                float v0 = acc[t][j][half * 2 + 0] + bias_sm[col];
                float v1 = acc[t][j][half * 2 + 1] + bias_sm[col + 1];
                if (MODE == 0) {
                    v0 = fmaxf(v0, 0.f); v1 = fmaxf(v1, 0.f);
                } else if (MODE == 1) {
                    float2 be = *(const float2*)(extra + (size_t)p * 128 + col);
                    float2 ga = *(const float2*)(extra + (size_t)p * 128 + 64 + col);
                    v0 = v0 * be.x + ga.x;
                    v1 = v1 * be.y + ga.y;
                } else { // MODE 3
                    float2 rs = *(const float2*)(extra + (size_t)p * 64 + col);
                    v0 = fmaxf(v0, 0.f) + rs.x;
                    v1 = fmaxf(v1, 0.f) + rs.y;
                }
                if (MODE == 3) {
                    *(float2*)(outf + (size_t)p * 64 + col) = make_float2(v0, v1);
                } else {
                    bf16 h0 = __float2bfloat16(v0), h1 = __float2bfloat16(v1);
                    bf16 l0 = __float2bfloat16(v0 - __bfloat162float(h0));
                    bf16 l1 = __float2bfloat16(v1 - __bfloat162float(h1));
                    uint32_t hp = (uint32_t)__bfloat16_as_ushort(h0) |
                                  ((uint32_t)__bfloat16_as_ushort(h1) << 16);
                    uint32_t lp = (uint32_t)__bfloat16_as_ushort(l0) |
                                  ((uint32_t)__bfloat16_as_ushort(l1) << 16);
                    *(uint32_t*)(outhi + (size_t)p * 64 + col) = hp;
                    *(uint32_t*)(outlo + (size_t)p * 64 + col) = lp;
                }
            }
        }
    }
}

// ---------------- launch ----------------
extern "C" void kernel_launch(void* const* d_in, const int* in_sizes, int n_in,
                              void* d_out, int out_size)
{
    const float* feats = (const float*)d_in[0];
    const float* cond  = (const float*)d_in[1];
    const float* W1a   = (const float*)d_in[2];
    const float* b1a   = (const float*)d_in[3];
    const float* W1b   = (const float*)d_in[4];
    const float* b1b   = (const float*)d_in[5];
    const float* W2a   = (const float*)d_in[6];
    const float* b2a   = (const float*)d_in[7];
    const float* W2b   = (const float*)d_in[8];
    const float* b2b   = (const float*)d_in[9];
    const int*   nbr   = (const int*)d_in[10];

    int P = in_sizes[0] / N_CH;
    float* out = (float*)d_out;

    bf16 *fhi, *flo, *ahi, *alo, *bhi, *blo, *whi, *wlo;
    cudaGetSymbolAddress((void**)&fhi, g_fhi);
    cudaGetSymbolAddress((void**)&flo, g_flo);
    cudaGetSymbolAddress((void**)&ahi, g_ahi);
    cudaGetSymbolAddress((void**)&alo, g_alo);
    cudaGetSymbolAddress((void**)&bhi, g_bhi);
    cudaGetSymbolAddress((void**)&blo, g_blo);
    cudaGetSymbolAddress((void**)&whi, g_whi);
    cudaGetSymbolAddress((void**)&wlo, g_wlo);

    cudaFuncSetAttribute(conv_mma<0>, cudaFuncAttributeMaxDynamicSharedMemorySize, SMEM_TOTAL);
    cudaFuncSetAttribute(conv_mma<1>, cudaFuncAttributeMaxDynamicSharedMemorySize, SMEM_TOTAL);
    cudaFuncSetAttribute(conv_mma<3>, cudaFuncAttributeMaxDynamicSharedMemorySize, SMEM_TOTAL);

    {
        dim3 g((27 * 4096 + 255) / 256, 4);
        prep_weights<<<g, 256>>>(W1a, W1b, W2a, W2b, whi, wlo);
    }
    prep_feats<<<(P * N_CH + 255) / 256, 256>>>(feats, fhi, flo, P * N_CH);

    const size_t LW = (size_t)27 * 4096;
    int grid = (P + 127) / 128;
    conv_mma<0><<<grid, 128, SMEM_TOTAL>>>(fhi, flo, nbr, whi + 0 * LW, wlo + 0 * LW,
                                           b1a, nullptr, nullptr, ahi, alo, P);
    conv_mma<1><<<grid, 128, SMEM_TOTAL>>>(ahi, alo, nbr, whi + 1 * LW, wlo + 1 * LW,
                                           b1b, cond, nullptr, bhi, blo, P);
    conv_mma<0><<<grid, 128, SMEM_TOTAL>>>(bhi, blo, nbr, whi + 2 * LW, wlo + 2 * LW,
                                           b2a, nullptr, nullptr, ahi, alo, P);
    conv_mma<3><<<grid, 128, SMEM_TOTAL>>>(ahi, alo, nbr, whi + 3 * LW, wlo + 3 * LW,
                                           b2b, feats, out, nullptr, nullptr, P);
}